// round 11
// baseline (speedup 1.0000x reference)
#include <cuda_runtime.h>
#include <cstdint>

// (32, 1024, 2048) fp32.  noisy = data + 0.1*noise; mask top-512 uniforms per row
// (ties at threshold -> lowest index first, matching jax.lax.top_k stability).
// out[0:N) = masked, out[N:2N) = mask_inverse.
// 2 rows per CTA, all loads issued at entry for maximal in-flight DRAM traffic.

#define D_DIM 2048
#define K_SEL 512
#define TPB   256
#define EPT   8          // D_DIM / TPB, contiguous per thread
#define FULLM 0xFFFFFFFFu
#define SENT  0xFFFFFFFFu

#define CP_ASYNC16(dst_u32, src_ptr) \
    asm volatile("cp.async.cg.shared.global [%0], [%1], 16;" :: "r"(dst_u32), "l"(src_ptr) : "memory")

__global__ __launch_bounds__(TPB, 6)
void obs_mask_kernel(const float* __restrict__ data,
                     const float* __restrict__ noise,
                     const float* __restrict__ rand_vals,
                     float* __restrict__ out_masked,
                     float* __restrict__ out_inv,
                     int rows)
{
    __shared__ float4   s_dn[2048];    // 32KB: per row 1024 float4 (data 512 | noise 512)
    __shared__ alignas(16) unsigned s_hist[256]; // fast path uses [0..127]; fallback all 256
    __shared__ unsigned s_cnt[8];
    __shared__ unsigned s_cand[64];
    __shared__ unsigned s_bc[2];       // {selected bin (or SENT), count strictly above bin}
    __shared__ unsigned s_res[2];      // {T bits, idxT}
    __shared__ unsigned s_n;

    const int tid  = threadIdx.x;
    const int lane = tid & 31;
    const int wid  = tid >> 5;
    const int row0 = blockIdx.x * 2;
    const unsigned idxBase = (unsigned)tid << 3;

    const size_t baseA = (size_t)row0 * D_DIM;
    const size_t baseB = baseA + D_DIM;
    const bool hasB = (row0 + 1) < rows;   // uniform across block

    // ---- rand loads for BOTH rows into registers (issued immediately) ----
    const uint4* rpA = reinterpret_cast<const uint4*>(rand_vals + baseA) + (tid << 1);
    const uint4* rpB = reinterpret_cast<const uint4*>(rand_vals + baseB) + (tid << 1);
    uint4 ra0 = __ldcs(rpA);
    uint4 ra1 = __ldcs(rpA + 1);
    uint4 rb0, rb1;
    if (hasB) { rb0 = __ldcs(rpB); rb1 = __ldcs(rpB + 1); }
    else      { rb0 = make_uint4(0,0,0,0); rb1 = make_uint4(0,0,0,0); }

    // ---- cp.async prefetch of data+noise for both rows (2 commit groups) ----
    {
        unsigned sbase = (unsigned)__cvta_generic_to_shared(s_dn);
        const float4* dpA = reinterpret_cast<const float4*>(data  + baseA) + (tid << 1);
        const float4* npA = reinterpret_cast<const float4*>(noise + baseA) + (tid << 1);
        unsigned dD = sbase + (unsigned)(tid * 32);
        unsigned dN = sbase + 8192u + (unsigned)(tid * 32);
        CP_ASYNC16(dD,       dpA);
        CP_ASYNC16(dD + 16u, dpA + 1);
        CP_ASYNC16(dN,       npA);
        CP_ASYNC16(dN + 16u, npA + 1);
        asm volatile("cp.async.commit_group;" ::: "memory");
        if (hasB) {
            const float4* dpB = reinterpret_cast<const float4*>(data  + baseB) + (tid << 1);
            const float4* npB = reinterpret_cast<const float4*>(noise + baseB) + (tid << 1);
            CP_ASYNC16(dD + 16384u, dpB);
            CP_ASYNC16(dD + 16400u, dpB + 1);
            CP_ASYNC16(dN + 16384u, npB);
            CP_ASYNC16(dN + 16400u, npB + 1);
        }
        asm volatile("cp.async.commit_group;" ::: "memory");
    }

    unsigned r[2][EPT] = {
        {ra0.x, ra0.y, ra0.z, ra0.w, ra1.x, ra1.y, ra1.z, ra1.w},
        {rb0.x, rb0.y, rb0.z, rb0.w, rb1.x, rb1.y, rb1.z, rb1.w}
    };

    #pragma unroll
    for (int row = 0; row < 2; ++row) {
        if (row == 1 && !hasB) break;           // uniform: whole block exits together
        const size_t base = (row == 0) ? baseA : baseB;

        // ---- zero 128-bin histogram + control words ----
        if (tid < 128) s_hist[tid] = 0;
        if (tid == 0) { s_n = 0; s_bc[0] = SENT; }
        __syncthreads();                         // barrier #1

        // ---- histogram over [0.5, 1.0): bin = t16 - 0x3F00 in [0,128) ----
        int big = 0;
        #pragma unroll
        for (int j = 0; j < EPT; ++j) {
            unsigned bin = (r[row][j] >> 16) - 0x3F00u;
            if (bin < 128u) atomicAdd(&s_hist[bin], 1u);
            big |= (r[row][j] >= 0x3F800000u);
        }
        int anyBig = __syncthreads_or(big);      // barrier #2

        bool generic = (anyBig != 0);

        if (!generic) {
            // ---- warp0: suffix scan of 128 bins (4 bins/lane) ----
            if (wid == 0) {
                uint4 h4 = reinterpret_cast<const uint4*>(s_hist)[lane];
                unsigned s3 = h4.w;
                unsigned s2 = h4.z + s3;
                unsigned s1 = h4.y + s2;
                unsigned s0 = h4.x + s1;
                unsigned inc = s0;
                #pragma unroll
                for (int off = 1; off < 32; off <<= 1) {
                    unsigned o = __shfl_down_sync(FULLM, inc, off);
                    if (lane + off < 32) inc += o;
                }
                unsigned above = inc - s0;
                unsigned S0 = above + s0, S1 = above + s1, S2 = above + s2, S3 = above + s3;
                if (S0 >= K_SEL && S0 - h4.x < K_SEL) { s_bc[0] = 4u*lane;    s_bc[1] = S0 - h4.x; }
                if (S1 >= K_SEL && S1 - h4.y < K_SEL) { s_bc[0] = 4u*lane+1u; s_bc[1] = S1 - h4.y; }
                if (S2 >= K_SEL && S2 - h4.z < K_SEL) { s_bc[0] = 4u*lane+2u; s_bc[1] = S2 - h4.z; }
                if (S3 >= K_SEL && S3 - h4.w < K_SEL) { s_bc[0] = 4u*lane+3u; s_bc[1] = S3 - h4.w; }
            }
            __syncthreads();                     // barrier #3

            if (s_bc[0] == SENT) {
                generic = true;
            } else {
                const unsigned t16sel = 0x3F00u + s_bc[0];
                const unsigned rem2   = K_SEL - s_bc[1];

                #pragma unroll
                for (int j = 0; j < EPT; ++j) {
                    if ((r[row][j] >> 16) == t16sel) {
                        unsigned key = ((r[row][j] & 0xFFFFu) << 11) | (2047u - (idxBase + j));
                        unsigned pos = atomicAdd(&s_n, 1u);
                        if (pos < 64u) s_cand[pos] = key;
                    }
                }
                __syncthreads();                 // barrier #4

                unsigned n = s_n;
                if (n <= 64u) {
                    if (wid == 0) {
                        unsigned k0 = (lane < (int)n)            ? s_cand[lane]      : 0u;
                        unsigned k1 = ((unsigned)lane + 32u < n) ? s_cand[lane + 32] : 0u;
                        unsigned c0 = 0, c1v = 0;
                        unsigned nn = n < 32u ? n : 32u;
                        for (unsigned i = 0; i < nn; ++i) {
                            unsigned b = __shfl_sync(FULLM, k0, i);
                            c0 += (b > k0); c1v += (b > k1);
                        }
                        if (n > 32u) {
                            unsigned n2 = n - 32u;
                            for (unsigned i = 0; i < n2; ++i) {
                                unsigned b = __shfl_sync(FULLM, k1, i);
                                c0 += (b > k0); c1v += (b > k1);
                            }
                        }
                        unsigned target = rem2 - 1u;
                        if ((unsigned)lane < n && c0 == target) {
                            s_res[0] = (t16sel << 16) | (k0 >> 11);
                            s_res[1] = 2047u - (k0 & 0x7FFu);
                        }
                        if ((unsigned)lane + 32u < n && c1v == target) {
                            s_res[0] = (t16sel << 16) | (k1 >> 11);
                            s_res[1] = 2047u - (k1 & 0x7FFu);
                        }
                    }
                    __syncthreads();             // barrier #5
                } else {
                    generic = true;
                }
            }
        }

        if (generic) {
            // ---- fully generic exact path: 4-pass byte radix + boundary index ----
            __syncthreads();
            unsigned prefix = 0, remG = K_SEL;
            for (int pass = 0; pass < 4; ++pass) {
                const int shift = 24 - 8 * pass;
                const unsigned pmask = (pass == 0) ? 0u : (0xFFFFFFFFu << (shift + 8));
                s_hist[tid] = 0;
                __syncthreads();
                for (int j = 0; j < EPT; ++j)
                    if ((r[row][j] & pmask) == prefix)
                        atomicAdd(&s_hist[(r[row][j] >> shift) & 255u], 1u);
                __syncthreads();
                unsigned h = s_hist[tid], v = h;
                for (int off = 1; off < 32; off <<= 1) {
                    unsigned o = __shfl_down_sync(FULLM, v, off);
                    if (lane + off < 32) v += o;
                }
                if (lane == 0) s_cnt[wid] = v;
                __syncthreads();
                unsigned addHi = 0;
                for (int w = 0; w < 8; ++w)
                    if (w > wid) addHi += s_cnt[w];
                unsigned S = v + addHi;
                if (S >= remG && S - h < remG) { s_bc[0] = (unsigned)tid; s_bc[1] = S - h; }
                __syncthreads();
                prefix |= s_bc[0] << shift;
                remG   -= s_bc[1];
                __syncthreads();
            }
            unsigned cnt = 0;
            for (int j = 0; j < EPT; ++j) cnt += (r[row][j] == prefix) ? 1u : 0u;
            unsigned iv = cnt;
            for (int off = 1; off < 32; off <<= 1) {
                unsigned o = __shfl_up_sync(FULLM, iv, off);
                if (lane >= off) iv += o;
            }
            if (lane == 31) s_cnt[wid] = iv;
            __syncthreads();
            unsigned wOff = 0;
            for (int w = 0; w < 8; ++w)
                if (w < wid) wOff += s_cnt[w];
            unsigned excl = wOff + iv - cnt;
            if (excl < remG && remG <= excl + cnt) {
                unsigned need = remG - excl, run = 0;
                for (int j = 0; j < EPT; ++j)
                    if (r[row][j] == prefix && ++run == need) {
                        s_res[0] = prefix;
                        s_res[1] = idxBase + j;
                    }
            }
            __syncthreads();
        }

        const unsigned T    = s_res[0];
        const unsigned idxT = s_res[1];

        // ---- mask predicates (independent of cp.async data) ----
        bool mk[EPT];
        #pragma unroll
        for (int j = 0; j < EPT; ++j)
            mk[j] = (r[row][j] > T) | ((r[row][j] == T) & (idxBase + (unsigned)j <= idxT));

        float4* mp = reinterpret_cast<float4*>(out_masked + base) + (tid << 1);
        float4* ip = reinterpret_cast<float4*>(out_inv    + base) + (tid << 1);

        __stcs(ip,     make_float4(mk[0] ? 0.f : 1.f, mk[1] ? 0.f : 1.f,
                                   mk[2] ? 0.f : 1.f, mk[3] ? 0.f : 1.f));
        __stcs(ip + 1, make_float4(mk[4] ? 0.f : 1.f, mk[5] ? 0.f : 1.f,
                                   mk[6] ? 0.f : 1.f, mk[7] ? 0.f : 1.f));

        // ---- wait for this row's cp.async group (row0: 1 may pend; row1: none) ----
        if (row == 0) asm volatile("cp.async.wait_group 1;" ::: "memory");
        else          asm volatile("cp.async.wait_group 0;" ::: "memory");

        const int so = row * 1024;               // float4 offset of this row's tile
        {
            float4 d0 = s_dn[so + tid * 2];
            float4 n0 = s_dn[so + 512 + tid * 2];
            __stcs(mp, make_float4(mk[0] ? 0.f : fmaf(0.1f, n0.x, d0.x),
                                   mk[1] ? 0.f : fmaf(0.1f, n0.y, d0.y),
                                   mk[2] ? 0.f : fmaf(0.1f, n0.z, d0.z),
                                   mk[3] ? 0.f : fmaf(0.1f, n0.w, d0.w)));
        }
        {
            float4 d1 = s_dn[so + tid * 2 + 1];
            float4 n1 = s_dn[so + 512 + tid * 2 + 1];
            __stcs(mp + 1, make_float4(mk[4] ? 0.f : fmaf(0.1f, n1.x, d1.x),
                                       mk[5] ? 0.f : fmaf(0.1f, n1.y, d1.y),
                                       mk[6] ? 0.f : fmaf(0.1f, n1.z, d1.z),
                                       mk[7] ? 0.f : fmaf(0.1f, n1.w, d1.w)));
        }
        // ---- re-sync before next row reuses s_res/s_hist (row 0 only) ----
        if (row == 0 && hasB) __syncthreads();
    }
}

extern "C" void kernel_launch(void* const* d_in, const int* in_sizes, int n_in,
                              void* d_out, int out_size)
{
    const float* data  = (const float*)d_in[0];
    const float* noise = (const float*)d_in[1];
    const float* rv    = (const float*)d_in[2];
    float* out = (float*)d_out;

    size_t n = (size_t)in_sizes[0];   // 32*1024*2048
    int rows = (int)(n / D_DIM);      // 32768
    int grid = (rows + 1) / 2;        // 2 rows per CTA

    obs_mask_kernel<<<grid, TPB>>>(data, noise, rv, out, out + n, rows);
}

// round 14
// speedup vs baseline: 1.0962x; 1.0962x over previous
#include <cuda_runtime.h>
#include <cstdint>

// (32, 1024, 2048) fp32.  noisy = data + 0.1*noise; mask top-512 uniforms per row
// (ties at threshold -> lowest index first, matching jax.lax.top_k stability).
// out[0:N) = masked, out[N:2N) = mask_inverse.

#define D_DIM 2048
#define K_SEL 512
#define TPB   256
#define EPT   8          // D_DIM / TPB, contiguous per thread
#define FULLM 0xFFFFFFFFu

#define CP_ASYNC16(dst_u32, src_ptr) \
    asm volatile("cp.async.cg.shared.global [%0], [%1], 16;" :: "r"(dst_u32), "l"(src_ptr) : "memory")

__global__ __launch_bounds__(TPB, 8)
void obs_mask_kernel(const float* __restrict__ data,
                     const float* __restrict__ noise,
                     const float* __restrict__ rand_vals,
                     float* __restrict__ out_masked,
                     float* __restrict__ out_inv)
{
    __shared__ float4   s_dn[1024];    // 16KB: [0,512) = data row, [512,1024) = noise row
    __shared__ unsigned s_hist[256];   // fast path uses [0..63]; fallback uses all 256
    __shared__ unsigned s_cnt[8];
    __shared__ unsigned s_cand[64];
    __shared__ unsigned s_bc[2];       // {selected t16 bin, count strictly above bin}
    __shared__ unsigned s_res[2];      // {T bits, idxT}
    __shared__ unsigned s_n;

    const int tid  = threadIdx.x;
    const int lane = tid & 31;
    const int wid  = tid >> 5;
    const size_t base = (size_t)blockIdx.x * D_DIM;
    const unsigned idxBase = (unsigned)tid << 3;

    // ---- rand loads into registers (needed immediately for selection) ----
    const uint4* rp = reinterpret_cast<const uint4*>(rand_vals + base) + (tid << 1);
    uint4 ra = __ldcs(rp);
    uint4 rb = __ldcs(rp + 1);

    // ---- cp.async prefetch of data+noise into smem: drains during selection,
    //      costs no registers. Each thread copies (and later reads) its own bytes.
    {
        unsigned sbase = (unsigned)__cvta_generic_to_shared(s_dn);
        const float4* dp = reinterpret_cast<const float4*>(data  + base) + (tid << 1);
        const float4* np = reinterpret_cast<const float4*>(noise + base) + (tid << 1);
        unsigned dD = sbase + (unsigned)(tid * 32);            // 2 float4 per thread
        unsigned dN = sbase + 8192u + (unsigned)(tid * 32);
        CP_ASYNC16(dD,       dp);
        CP_ASYNC16(dD + 16u, dp + 1);
        CP_ASYNC16(dN,       np);
        CP_ASYNC16(dN + 16u, np + 1);
        asm volatile("cp.async.commit_group;" ::: "memory");
    }

    unsigned r[EPT] = {ra.x, ra.y, ra.z, ra.w, rb.x, rb.y, rb.z, rb.w};

    // ---- cheap exact band census: c1 = #{v>=0.75}, c2 = #{v>=0.5}, any >= 1.0 ----
    unsigned cpk = 0;   // c1 in low 16, c2 in high 16
    int big = 0;
    #pragma unroll
    for (int j = 0; j < EPT; ++j) {
        cpk += (r[j] >= 0x3F400000u) ? 1u : 0u;
        cpk += (r[j] >= 0x3F000000u) ? 0x10000u : 0u;
        big |= (r[j] >= 0x3F800000u);
    }
    #pragma unroll
    for (int off = 16; off >= 1; off >>= 1)
        cpk += __shfl_down_sync(FULLM, cpk, off);
    if (lane == 0) s_cnt[wid] = cpk;
    if (tid < 64) s_hist[tid] = 0;
    if (tid == 0) s_n = 0;

    int anyBig = __syncthreads_or(big);          // barrier #1

    unsigned csum = 0;
    #pragma unroll
    for (int w = 0; w < 8; ++w) csum += s_cnt[w];
    const unsigned c1 = csum & 0xFFFFu;
    const unsigned c2 = csum >> 16;

    bool generic = (anyBig != 0);
    unsigned lo16 = 0, remBand = 0;
    if (!generic) {
        if (c1 >= K_SEL)      { lo16 = 0x3F40u; remBand = K_SEL; }
        else if (c2 >= K_SEL) { lo16 = 0x3F00u; remBand = K_SEL - c1; }
        else                  { generic = true; }
    }

    if (!generic) {
        // ---- 64-bin histogram over the quarter-band only (~2 atomics/thread) ----
        #pragma unroll
        for (int j = 0; j < EPT; ++j) {
            unsigned bin = (r[j] >> 16) - lo16;
            if (bin < 64u) atomicAdd(&s_hist[bin], 1u);
        }
        __syncthreads();                         // barrier #2

        // ---- warp0: suffix scan of 64 bins, pick crossing bin ----
        if (wid == 0) {
            uint2 h2 = reinterpret_cast<const uint2*>(s_hist)[lane];  // bins 2l, 2l+1
            unsigned s1 = h2.y;
            unsigned s0 = h2.x + s1;
            unsigned inc = s0;
            #pragma unroll
            for (int off = 1; off < 32; off <<= 1) {
                unsigned o = __shfl_down_sync(FULLM, inc, off);
                if (lane + off < 32) inc += o;
            }
            unsigned abovePairs = inc - s0;
            unsigned S_hi = abovePairs + s1;      // bin 2l+1
            unsigned S_lo = abovePairs + s0;      // bin 2l
            if (S_hi >= remBand && S_hi - h2.y < remBand) {
                s_bc[0] = lo16 + 2u * lane + 1u;  s_bc[1] = S_hi - h2.y;
            }
            if (S_lo >= remBand && S_lo - h2.x < remBand) {
                s_bc[0] = lo16 + 2u * lane;       s_bc[1] = S_lo - h2.x;
            }
        }
        __syncthreads();                         // barrier #3

        const unsigned t16sel = s_bc[0];
        const unsigned rem2   = remBand - s_bc[1];   // rank within crossing bin, >= 1

        // ---- collect crossing-bin candidates as packed keys ----
        #pragma unroll
        for (int j = 0; j < EPT; ++j) {
            if ((r[j] >> 16) == t16sel) {
                unsigned key = ((r[j] & 0xFFFFu) << 11) | (2047u - (idxBase + j));
                unsigned pos = atomicAdd(&s_n, 1u);
                if (pos < 64u) s_cand[pos] = key;
            }
        }
        __syncthreads();                         // barrier #4

        unsigned n = s_n;
        if (n <= 64u) {
            // ---- warp0: exact rank-(rem2) select among n distinct keys ----
            if (wid == 0) {
                unsigned k0 = (lane < (int)n)        ? s_cand[lane]      : 0u;
                unsigned k1 = ((unsigned)lane + 32u < n) ? s_cand[lane + 32] : 0u;
                unsigned r0 = 0, r1 = 0;
                unsigned nn = n < 32u ? n : 32u;
                for (unsigned i = 0; i < nn; ++i) {
                    unsigned b = __shfl_sync(FULLM, k0, i);
                    r0 += (b > k0); r1 += (b > k1);
                }
                if (n > 32u) {
                    unsigned n2 = n - 32u;
                    for (unsigned i = 0; i < n2; ++i) {
                        unsigned b = __shfl_sync(FULLM, k1, i);
                        r0 += (b > k0); r1 += (b > k1);
                    }
                }
                unsigned target = rem2 - 1u;
                if ((unsigned)lane < n && r0 == target) {
                    s_res[0] = (t16sel << 16) | (k0 >> 11);
                    s_res[1] = 2047u - (k0 & 0x7FFu);
                }
                if ((unsigned)lane + 32u < n && r1 == target) {
                    s_res[0] = (t16sel << 16) | (k1 >> 11);
                    s_res[1] = 2047u - (k1 & 0x7FFu);
                }
            }
            __syncthreads();                     // barrier #5
        } else {
            generic = true;                      // block-uniform
        }
    }

    if (generic) {
        // ---- fully generic exact path: 4-pass byte radix + boundary index ----
        __syncthreads();
        unsigned prefix = 0, remG = K_SEL;
        for (int pass = 0; pass < 4; ++pass) {
            const int shift = 24 - 8 * pass;
            const unsigned pmask = (pass == 0) ? 0u : (0xFFFFFFFFu << (shift + 8));
            s_hist[tid] = 0;
            __syncthreads();
            for (int j = 0; j < EPT; ++j)
                if ((r[j] & pmask) == prefix)
                    atomicAdd(&s_hist[(r[j] >> shift) & 255u], 1u);
            __syncthreads();
            unsigned h = s_hist[tid], v = h;
            for (int off = 1; off < 32; off <<= 1) {
                unsigned o = __shfl_down_sync(FULLM, v, off);
                if (lane + off < 32) v += o;
            }
            if (lane == 0) s_cnt[wid] = v;
            __syncthreads();
            unsigned addHi = 0;
            for (int w = 0; w < 8; ++w)
                if (w > wid) addHi += s_cnt[w];
            unsigned S = v + addHi;
            if (S >= remG && S - h < remG) { s_bc[0] = (unsigned)tid; s_bc[1] = S - h; }
            __syncthreads();
            prefix |= s_bc[0] << shift;
            remG   -= s_bc[1];
            __syncthreads();
        }
        // locate idxT: index of the remG-th equal-to-prefix element (ascending index)
        unsigned cnt = 0;
        for (int j = 0; j < EPT; ++j) cnt += (r[j] == prefix) ? 1u : 0u;
        unsigned iv = cnt;
        for (int off = 1; off < 32; off <<= 1) {
            unsigned o = __shfl_up_sync(FULLM, iv, off);
            if (lane >= off) iv += o;
        }
        if (lane == 31) s_cnt[wid] = iv;
        __syncthreads();
        unsigned wOff = 0;
        for (int w = 0; w < 8; ++w)
            if (w < wid) wOff += s_cnt[w];
        unsigned excl = wOff + iv - cnt;
        if (excl < remG && remG <= excl + cnt) {
            unsigned need = remG - excl, run = 0;
            for (int j = 0; j < EPT; ++j)
                if (r[j] == prefix && ++run == need) {
                    s_res[0] = prefix;
                    s_res[1] = idxBase + j;
                }
        }
        __syncthreads();
    }

    const unsigned T    = s_res[0];
    const unsigned idxT = s_res[1];

    // ---- wait for own cp.async data (thread-local smem; no block sync needed) ----
    asm volatile("cp.async.wait_group 0;" ::: "memory");

    float4* mp = reinterpret_cast<float4*>(out_masked + base) + (tid << 1);
    float4* ip = reinterpret_cast<float4*>(out_inv    + base) + (tid << 1);

    // compute mask predicates first (frees r early, keeps live set small)
    bool mk[EPT];
    #pragma unroll
    for (int j = 0; j < EPT; ++j)
        mk[j] = (r[j] > T) | ((r[j] == T) & (idxBase + (unsigned)j <= idxT));

    __stcs(ip,     make_float4(mk[0] ? 0.f : 1.f, mk[1] ? 0.f : 1.f,
                               mk[2] ? 0.f : 1.f, mk[3] ? 0.f : 1.f));
    __stcs(ip + 1, make_float4(mk[4] ? 0.f : 1.f, mk[5] ? 0.f : 1.f,
                               mk[6] ? 0.f : 1.f, mk[7] ? 0.f : 1.f));

    {
        float4 d0 = s_dn[tid * 2];
        float4 n0 = s_dn[512 + tid * 2];
        __stcs(mp, make_float4(mk[0] ? 0.f : fmaf(0.1f, n0.x, d0.x),
                               mk[1] ? 0.f : fmaf(0.1f, n0.y, d0.y),
                               mk[2] ? 0.f : fmaf(0.1f, n0.z, d0.z),
                               mk[3] ? 0.f : fmaf(0.1f, n0.w, d0.w)));
    }
    {
        float4 d1 = s_dn[tid * 2 + 1];
        float4 n1 = s_dn[512 + tid * 2 + 1];
        __stcs(mp + 1, make_float4(mk[4] ? 0.f : fmaf(0.1f, n1.x, d1.x),
                                   mk[5] ? 0.f : fmaf(0.1f, n1.y, d1.y),
                                   mk[6] ? 0.f : fmaf(0.1f, n1.z, d1.z),
                                   mk[7] ? 0.f : fmaf(0.1f, n1.w, d1.w)));
    }
}

extern "C" void kernel_launch(void* const* d_in, const int* in_sizes, int n_in,
                              void* d_out, int out_size)
{
    const float* data  = (const float*)d_in[0];
    const float* noise = (const float*)d_in[1];
    const float* rv    = (const float*)d_in[2];
    float* out = (float*)d_out;

    size_t n = (size_t)in_sizes[0];   // 32*1024*2048
    int rows = (int)(n / D_DIM);      // 32768

    obs_mask_kernel<<<rows, TPB>>>(data, noise, rv, out, out + n);
}